// round 1
// baseline (speedup 1.0000x reference)
#include <cuda_runtime.h>
#include <math.h>

#define T_ 6
#define N_ 20000
#define E_ 400000
#define F_ 64
#define C_ 64
#define H_ 128
#define BIG_ 0x3fffffff

// ---------------- scratch (device globals; no allocation) ----------------
__device__ __align__(128) int   g_lvl[N_];
__device__ __align__(128) int   g_count[N_];
__device__ __align__(128) int   g_rowptr[N_ + 1];
__device__ __align__(128) int   g_cursor[N_];
__device__ __align__(128) int   g_csrsrc[E_];
__device__ __align__(128) float g_dinv[N_];
__device__ __align__(128) float g_buf1[N_ * H_];
__device__ __align__(128) float g_buf2[N_ * H_];
__device__ unsigned long long   g_argmax;
__device__ __align__(128) float g_seq[T_ * H_];

// ---------------- per-snapshot setup ----------------
__global__ void k_reset() {
    int i = blockIdx.x * blockDim.x + threadIdx.x;
    if (i < N_) { g_lvl[i] = BIG_; g_count[i] = 0; }
    if (i == 0) g_argmax = 0ULL;
}

__global__ void k_seed(const int* __restrict__ tgt) {
    int i = threadIdx.x;
    if (i < C_) g_lvl[tgt[i]] = 0;
}

// Level-stamped BFS iteration k: a node is "in" at start of iter k iff lvl < k.
// Writes during iter k are exactly value k, so non-atomic reads cannot cause
// over-propagation (predicate lvl<k only sees earlier iterations).
__global__ void k_prop(const int* __restrict__ src, const int* __restrict__ dst, int k) {
    int i = blockIdx.x * blockDim.x + threadIdx.x;
    if (i >= E_) return;
    int s = src[i], d = dst[i];
    int ls = g_lvl[s], ld = g_lvl[d];
    if (ls < k && ld > k) atomicMin(&g_lvl[d], k);
    if (ld < k && ls > k) atomicMin(&g_lvl[s], k);
}

// in-degree over subgraph edges (directed, dst side) == CSR histogram
__global__ void k_count(const int* __restrict__ src, const int* __restrict__ dst) {
    int i = blockIdx.x * blockDim.x + threadIdx.x;
    if (i >= E_) return;
    int s = src[i], d = dst[i];
    if (g_lvl[s] < BIG_ && g_lvl[d] < BIG_) atomicAdd(&g_count[d], 1);
}

// single-block exclusive scan over g_count -> rowptr/cursor; also dinv.
// deg = edge_in_degree + 1 (self loop) for subgraph nodes, dinv = rsqrt(deg).
__global__ void k_scan() {
    const int CH = 20;  // 1024 * 20 >= 20000
    __shared__ int s[1024];
    int tid = threadIdx.x;
    int base = tid * CH;
    int loc[CH];
    int sum = 0;
#pragma unroll
    for (int i = 0; i < CH; i++) {
        int idx = base + i;
        int c = (idx < N_) ? g_count[idx] : 0;
        loc[i] = sum;
        sum += c;
    }
    s[tid] = sum;
    __syncthreads();
    for (int off = 1; off < 1024; off <<= 1) {
        int v = (tid >= off) ? s[tid - off] : 0;
        __syncthreads();
        s[tid] += v;
        __syncthreads();
    }
    int excl = s[tid] - sum;
#pragma unroll
    for (int i = 0; i < CH; i++) {
        int idx = base + i;
        if (idx < N_) {
            int o = excl + loc[i];
            g_rowptr[idx] = o;
            g_cursor[idx] = o;
            int lv = g_lvl[idx];
            g_dinv[idx] = (lv < BIG_) ? rsqrtf((float)g_count[idx] + 1.0f) : 0.0f;
        }
    }
    if (tid == 1023) g_rowptr[N_] = s[1023];
}

__global__ void k_fill(const int* __restrict__ src, const int* __restrict__ dst) {
    int i = blockIdx.x * blockDim.x + threadIdx.x;
    if (i >= E_) return;
    int s = src[i], d = dst[i];
    if (g_lvl[s] < BIG_ && g_lvl[d] < BIG_) {
        int p = atomicAdd(&g_cursor[d], 1);
        g_csrsrc[p] = s;
    }
}

// ---------------- GEMM: out[n,:] = dinv[n] * (A[n,:] @ W  (+ labels)) ----------------
// tile 64 rows x 128 cols, 256 threads, 8x4 micro-tile, K-chunks of 32.
#define BM 64
#define KC 32
__global__ void __launch_bounds__(256) k_gemm(const float* __restrict__ A, int K,
                                              const float* __restrict__ W, int addLabels,
                                              float* __restrict__ out) {
    __shared__ float As[KC][BM + 4];
    __shared__ float Bs[KC][H_];
    int tid = threadIdx.x;
    int tc = tid & 31;       // col group: cols 4*tc .. 4*tc+3
    int tr = tid >> 5;       // row group: rows tr*8 .. tr*8+7
    int m0 = blockIdx.x * BM;

    float acc[8][4];
#pragma unroll
    for (int i = 0; i < 8; i++)
#pragma unroll
        for (int j = 0; j < 4; j++) acc[i][j] = 0.0f;

    for (int kb = 0; kb < K; kb += KC) {
        // load A tile (64 x 32) as float4, transposed into As[k][row]
#pragma unroll
        for (int i = 0; i < 2; i++) {
            int e = tid + i * 256;
            int r = e >> 3;
            int kq = (e & 7) * 4;
            int gr = m0 + r;
            float4 v = make_float4(0.f, 0.f, 0.f, 0.f);
            if (gr < N_) v = *(const float4*)&A[(size_t)gr * K + kb + kq];
            As[kq + 0][r] = v.x;
            As[kq + 1][r] = v.y;
            As[kq + 2][r] = v.z;
            As[kq + 3][r] = v.w;
        }
        // load W tile (32 x 128)
#pragma unroll
        for (int i = 0; i < 4; i++) {
            int e = tid + i * 256;
            int kr = e >> 5;
            int cq = (e & 31) * 4;
            *(float4*)&Bs[kr][cq] = *(const float4*)&W[(size_t)(kb + kr) * H_ + cq];
        }
        __syncthreads();
#pragma unroll
        for (int k = 0; k < KC; k++) {
            float4 b = *(float4*)&Bs[k][tc * 4];
            float a[8];
#pragma unroll
            for (int i = 0; i < 8; i++) a[i] = As[k][tr * 8 + i];
#pragma unroll
            for (int i = 0; i < 8; i++) {
                acc[i][0] = fmaf(a[i], b.x, acc[i][0]);
                acc[i][1] = fmaf(a[i], b.y, acc[i][1]);
                acc[i][2] = fmaf(a[i], b.z, acc[i][2]);
                acc[i][3] = fmaf(a[i], b.w, acc[i][3]);
            }
        }
        __syncthreads();
    }

    float4 w64 = make_float4(0.f, 0.f, 0.f, 0.f);
    float4 w65 = make_float4(0.f, 0.f, 0.f, 0.f);
    if (addLabels) {
        w64 = *(const float4*)&W[(size_t)64 * H_ + tc * 4];
        w65 = *(const float4*)&W[(size_t)65 * H_ + tc * 4];
    }
#pragma unroll
    for (int i = 0; i < 8; i++) {
        int r = m0 + tr * 8 + i;
        if (r >= N_) break;
        float e0 = acc[i][0], e1 = acc[i][1], e2 = acc[i][2], e3 = acc[i][3];
        if (addLabels) {
            int lv = g_lvl[r];
            float l0 = (lv == 0) ? 1.0f : 0.0f;
            float l1 = (lv > 0 && lv < BIG_) ? 1.0f : 0.0f;
            e0 += l0 * w64.x + l1 * w65.x;
            e1 += l0 * w64.y + l1 * w65.y;
            e2 += l0 * w64.z + l1 * w65.z;
            e3 += l0 * w64.w + l1 * w65.w;
        }
        float d = g_dinv[r];
        float4 o = make_float4(e0 * d, e1 * d, e2 * d, e3 * d);
        *(float4*)&out[(size_t)r * H_ + tc * 4] = o;
    }
}

// ---------------- SpMM + combine: out[n,c] = relu(dinv[n]*(sum g[src,c] + g[n,c]) + b[c]) ----
__global__ void __launch_bounds__(128) k_spmm(const float* __restrict__ g,
                                              const float* __restrict__ bias,
                                              float* __restrict__ out) {
    int row = blockIdx.x;
    int c = threadIdx.x;
    int s0 = g_rowptr[row], s1 = g_rowptr[row + 1];
    __shared__ int srcs[128];
    float a0 = 0.f, a1 = 0.f, a2 = 0.f, a3 = 0.f;
    for (int base = s0; base < s1; base += 128) {
        int nn = min(128, s1 - base);
        if (c < nn) srcs[c] = g_csrsrc[base + c];
        __syncthreads();
        int j = 0;
        for (; j + 4 <= nn; j += 4) {
            a0 += g[(size_t)srcs[j] * H_ + c];
            a1 += g[(size_t)srcs[j + 1] * H_ + c];
            a2 += g[(size_t)srcs[j + 2] * H_ + c];
            a3 += g[(size_t)srcs[j + 3] * H_ + c];
        }
        for (; j < nn; j++) a0 += g[(size_t)srcs[j] * H_ + c];
        __syncthreads();
    }
    float acc = (a0 + a1) + (a2 + a3);
    float d = g_dinv[row];
    float v = fmaf(d, acc + g[(size_t)row * H_ + c], bias[c]);
    out[(size_t)row * H_ + c] = fmaxf(v, 0.0f);
}

// ---------------- argmax over subgraph of h2[:, H-1] (first-index tie-break) ----------------
__global__ void k_argmax(const float* __restrict__ h2) {
    int i = blockIdx.x * blockDim.x + threadIdx.x;
    unsigned long long p = 0ULL;
    if (i < N_ && g_dinv[i] > 0.0f) {
        float v = h2[(size_t)i * H_ + (H_ - 1)];  // relu'd -> >= 0, bits monotone
        p = ((unsigned long long)__float_as_uint(v) << 32) |
            (unsigned int)(0x7fffffff - i);
    }
    __shared__ unsigned long long s[256];
    s[threadIdx.x] = p;
    __syncthreads();
    for (int off = 128; off; off >>= 1) {
        if (threadIdx.x < off) {
            unsigned long long o = s[threadIdx.x + off];
            if (o > s[threadIdx.x]) s[threadIdx.x] = o;
        }
        __syncthreads();
    }
    if (threadIdx.x == 0) atomicMax(&g_argmax, s[0]);
}

__global__ void k_extract(const float* __restrict__ h2, int t) {
    int top = 0x7fffffff - (int)(g_argmax & 0x7fffffffULL);
    g_seq[t * H_ + threadIdx.x] = h2[(size_t)top * H_ + threadIdx.x];
}

// ---------------- GRU + MLP head ----------------
__device__ __forceinline__ float warp_sum(float v) {
    v += __shfl_down_sync(0xffffffffu, v, 16);
    v += __shfl_down_sync(0xffffffffu, v, 8);
    v += __shfl_down_sync(0xffffffffu, v, 4);
    v += __shfl_down_sync(0xffffffffu, v, 2);
    v += __shfl_down_sync(0xffffffffu, v, 1);
    return v;
}

__global__ void __launch_bounds__(128) k_final(const float* __restrict__ Wih,
                                               const float* __restrict__ Whh,
                                               const float* __restrict__ bih,
                                               const float* __restrict__ bhh,
                                               const float* __restrict__ Wc1,
                                               const float* __restrict__ bc1,
                                               const float* __restrict__ Wc2,
                                               const float* __restrict__ bc2,
                                               float* __restrict__ out) {
    __shared__ float h[H_], xt[H_], sgi[3 * H_], sgh[3 * H_], hid[H_ / 2];
    int tid = threadIdx.x, lane = tid & 31, w = tid >> 5;
    h[tid] = 0.0f;
    __syncthreads();
    for (int t = 0; t < T_; t++) {
        xt[tid] = g_seq[t * H_ + tid];
        __syncthreads();
        for (int o = w; o < 3 * H_; o += 4) {
            float si = 0.f, sh = 0.f;
            for (int k = lane; k < H_; k += 32) {
                si += xt[k] * Wih[(size_t)o * H_ + k];
                sh += h[k] * Whh[(size_t)o * H_ + k];
            }
            si = warp_sum(si);
            sh = warp_sum(sh);
            if (lane == 0) {
                sgi[o] = si + bih[o];
                sgh[o] = sh + bhh[o];
            }
        }
        __syncthreads();
        float r = 1.0f / (1.0f + expf(-(sgi[tid] + sgh[tid])));
        float z = 1.0f / (1.0f + expf(-(sgi[tid + H_] + sgh[tid + H_])));
        float n = tanhf(sgi[tid + 2 * H_] + r * sgh[tid + 2 * H_]);
        float hn = (1.0f - z) * n + z * h[tid];
        __syncthreads();
        h[tid] = hn;
        __syncthreads();
    }
    if (tid < H_ / 2) {
        float s = bc1[tid];
        for (int k = 0; k < H_; k++) s += h[k] * Wc1[(size_t)k * (H_ / 2) + tid];
        hid[tid] = fmaxf(s, 0.0f);
    }
    __syncthreads();
    if (tid == 0) {
        float s = bc2[0];
        for (int j = 0; j < H_ / 2; j++) s += hid[j] * Wc2[j];
        out[0] = 1.0f / (1.0f + expf(-s));
    }
}

// ---------------- launch ----------------
extern "C" void kernel_launch(void* const* d_in, const int* in_sizes, int n_in,
                              void* d_out, int out_size) {
    const float* x   = (const float*)d_in[0];
    const int*   ei  = (const int*)d_in[1];
    const int*   tgt = (const int*)d_in[2];
    const float* W1  = (const float*)d_in[3];
    const float* b1  = (const float*)d_in[4];
    const float* W2  = (const float*)d_in[5];
    const float* b2  = (const float*)d_in[6];
    const float* Wih = (const float*)d_in[7];
    const float* Whh = (const float*)d_in[8];
    const float* bih = (const float*)d_in[9];
    const float* bhh = (const float*)d_in[10];
    const float* Wc1 = (const float*)d_in[11];
    const float* bc1 = (const float*)d_in[12];
    const float* Wc2 = (const float*)d_in[13];
    const float* bc2 = (const float*)d_in[14];
    float* out = (float*)d_out;

    float *buf1 = nullptr, *buf2 = nullptr;
    cudaGetSymbolAddress((void**)&buf1, g_buf1);
    cudaGetSymbolAddress((void**)&buf2, g_buf2);

    const int GN = (N_ + 255) / 256;
    const int GE = (E_ + 255) / 256;
    const int GM = (N_ + BM - 1) / BM;

    for (int t = 0; t < T_; t++) {
        const int* src = ei + (size_t)t * 2 * E_;
        const int* dst = src + E_;
        const int* tg  = tgt + t * C_;
        const float* xt = x + (size_t)t * N_ * F_;

        k_reset<<<GN, 256>>>();
        k_seed<<<1, 64>>>(tg);
        k_prop<<<GE, 256>>>(src, dst, 1);
        k_prop<<<GE, 256>>>(src, dst, 2);
        k_count<<<GE, 256>>>(src, dst);
        k_scan<<<1, 1024>>>();
        k_fill<<<GE, 256>>>(src, dst);

        k_gemm<<<GM, 256>>>(xt, F_, W1, 1, buf1);      // g1 = dinv * (xl @ W1)
        k_spmm<<<N_, 128>>>(buf1, b1, buf2);           // h1
        k_gemm<<<GM, 256>>>(buf2, H_, W2, 0, buf1);    // g2 = dinv * (h1 @ W2)
        k_spmm<<<N_, 128>>>(buf1, b2, buf2);           // h2
        k_argmax<<<GN, 256>>>(buf2);
        k_extract<<<1, 128>>>(buf2, t);
    }
    k_final<<<1, 128>>>(Wih, Whh, bih, bhh, Wc1, bc1, Wc2, bc2, out);
}

// round 3
// speedup vs baseline: 1.1966x; 1.1966x over previous
#include <cuda_runtime.h>
#include <math.h>

#define T_ 6
#define N_ 20000
#define E_ 400000
#define F_ 64
#define C_ 64
#define H_ 128
#define BIG_ 0x3fffffff

// ---------------- scratch (device globals; no allocation) ----------------
__device__ __align__(128) int   g_lvl[T_][N_];
__device__ __align__(128) int   g_count[T_][N_];
__device__ __align__(128) int   g_rowptr[T_][N_ + 1];
__device__ __align__(128) int   g_cursor[T_][N_];
__device__ __align__(128) int   g_csrsrc[T_][E_];
__device__ __align__(128) float g_dinv[T_][N_];
__device__ __align__(128) float g_buf1[T_][N_ * H_];
__device__ __align__(128) float g_buf2[T_][N_ * H_];
__device__ unsigned long long   g_argmax[T_];
__device__ __align__(128) float g_seq[T_ * H_];

// ---------------- per-snapshot setup (batched over t = blockIdx.y) ----------------
__global__ void k_reset() {
    int t = blockIdx.y;
    int i = blockIdx.x * blockDim.x + threadIdx.x;
    if (i < N_) { g_lvl[t][i] = BIG_; g_count[t][i] = 0; }
    if (i == 0) g_argmax[t] = 0ULL;
}

__global__ void k_seed(const int* __restrict__ tgt) {
    int t = blockIdx.x;
    int i = threadIdx.x;
    if (i < C_) g_lvl[t][tgt[t * C_ + i]] = 0;
}

// Level-stamped BFS iteration k: a node is "in" at start of iter k iff lvl < k.
// Writes during iter k are exactly value k, so non-atomic reads cannot cause
// over-propagation (predicate lvl<k only sees earlier iterations).
__global__ void k_prop(const int* __restrict__ ei, int k) {
    int t = blockIdx.y;
    int i = blockIdx.x * blockDim.x + threadIdx.x;
    if (i >= E_) return;
    const int* src = ei + (size_t)t * 2 * E_;
    const int* dst = src + E_;
    int s = src[i], d = dst[i];
    int ls = g_lvl[t][s], ld = g_lvl[t][d];
    if (ls < k && ld > k) atomicMin(&g_lvl[t][d], k);
    if (ld < k && ls > k) atomicMin(&g_lvl[t][s], k);
}

// in-degree over subgraph edges (directed, dst side) == CSR histogram
__global__ void k_count(const int* __restrict__ ei) {
    int t = blockIdx.y;
    int i = blockIdx.x * blockDim.x + threadIdx.x;
    if (i >= E_) return;
    const int* src = ei + (size_t)t * 2 * E_;
    const int* dst = src + E_;
    int s = src[i], d = dst[i];
    if (g_lvl[t][s] < BIG_ && g_lvl[t][d] < BIG_) atomicAdd(&g_count[t][d], 1);
}

// per-snapshot single-block exclusive scan over g_count -> rowptr/cursor; also dinv.
// deg = edge_in_degree + 1 (self loop) for subgraph nodes, dinv = rsqrt(deg).
__global__ void k_scan() {
    int t = blockIdx.x;
    const int CH = 20;  // 1024 * 20 >= 20000
    __shared__ int s[1024];
    int tid = threadIdx.x;
    int base = tid * CH;
    int loc[CH];
    int sum = 0;
#pragma unroll
    for (int i = 0; i < CH; i++) {
        int idx = base + i;
        int c = (idx < N_) ? g_count[t][idx] : 0;
        loc[i] = sum;
        sum += c;
    }
    s[tid] = sum;
    __syncthreads();
    for (int off = 1; off < 1024; off <<= 1) {
        int v = (tid >= off) ? s[tid - off] : 0;
        __syncthreads();
        s[tid] += v;
        __syncthreads();
    }
    int excl = s[tid] - sum;
#pragma unroll
    for (int i = 0; i < CH; i++) {
        int idx = base + i;
        if (idx < N_) {
            int o = excl + loc[i];
            g_rowptr[t][idx] = o;
            g_cursor[t][idx] = o;
            int lv = g_lvl[t][idx];
            g_dinv[t][idx] = (lv < BIG_) ? rsqrtf((float)g_count[t][idx] + 1.0f) : 0.0f;
        }
    }
    if (tid == 1023) g_rowptr[t][N_] = s[1023];
}

__global__ void k_fill(const int* __restrict__ ei) {
    int t = blockIdx.y;
    int i = blockIdx.x * blockDim.x + threadIdx.x;
    if (i >= E_) return;
    const int* src = ei + (size_t)t * 2 * E_;
    const int* dst = src + E_;
    int s = src[i], d = dst[i];
    if (g_lvl[t][s] < BIG_ && g_lvl[t][d] < BIG_) {
        int p = atomicAdd(&g_cursor[t][d], 1);
        g_csrsrc[t][p] = s;
    }
}

// ---------------- GEMM: out[n,:] = dinv[n] * (A[n,:] @ W  (+ labels)) ----------------
// tile 64 rows x 128 cols, 256 threads, 8x4 micro-tile, K-chunks of 32.
// Batched over snapshots: blockIdx.y = t; A/out strided by N_*K / N_*H_.
#define BM 64
#define KC 32
__global__ void __launch_bounds__(256) k_gemm(const float* __restrict__ Abase, int K,
                                              const float* __restrict__ W, int addLabels,
                                              float* __restrict__ outBase) {
    int t = blockIdx.y;
    const float* A = Abase + (size_t)t * N_ * K;
    float* out = outBase + (size_t)t * N_ * H_;

    __shared__ float As[KC][BM + 4];
    __shared__ float Bs[KC][H_];
    int tid = threadIdx.x;
    int tc = tid & 31;       // col group: cols 4*tc .. 4*tc+3
    int tr = tid >> 5;       // row group: rows tr*8 .. tr*8+7
    int m0 = blockIdx.x * BM;

    float acc[8][4];
#pragma unroll
    for (int i = 0; i < 8; i++)
#pragma unroll
        for (int j = 0; j < 4; j++) acc[i][j] = 0.0f;

    for (int kb = 0; kb < K; kb += KC) {
        // load A tile (64 x 32) as float4, transposed into As[k][row]
#pragma unroll
        for (int i = 0; i < 2; i++) {
            int e = tid + i * 256;
            int r = e >> 3;
            int kq = (e & 7) * 4;
            int gr = m0 + r;
            float4 v = make_float4(0.f, 0.f, 0.f, 0.f);
            if (gr < N_) v = *(const float4*)&A[(size_t)gr * K + kb + kq];
            As[kq + 0][r] = v.x;
            As[kq + 1][r] = v.y;
            As[kq + 2][r] = v.z;
            As[kq + 3][r] = v.w;
        }
        // load W tile (32 x 128)
#pragma unroll
        for (int i = 0; i < 4; i++) {
            int e = tid + i * 256;
            int kr = e >> 5;
            int cq = (e & 31) * 4;
            *(float4*)&Bs[kr][cq] = *(const float4*)&W[(size_t)(kb + kr) * H_ + cq];
        }
        __syncthreads();
#pragma unroll
        for (int k = 0; k < KC; k++) {
            float4 b = *(float4*)&Bs[k][tc * 4];
            float a[8];
#pragma unroll
            for (int i = 0; i < 8; i++) a[i] = As[k][tr * 8 + i];
#pragma unroll
            for (int i = 0; i < 8; i++) {
                acc[i][0] = fmaf(a[i], b.x, acc[i][0]);
                acc[i][1] = fmaf(a[i], b.y, acc[i][1]);
                acc[i][2] = fmaf(a[i], b.z, acc[i][2]);
                acc[i][3] = fmaf(a[i], b.w, acc[i][3]);
            }
        }
        __syncthreads();
    }

    float4 w64 = make_float4(0.f, 0.f, 0.f, 0.f);
    float4 w65 = make_float4(0.f, 0.f, 0.f, 0.f);
    if (addLabels) {
        w64 = *(const float4*)&W[(size_t)64 * H_ + tc * 4];
        w65 = *(const float4*)&W[(size_t)65 * H_ + tc * 4];
    }
#pragma unroll
    for (int i = 0; i < 8; i++) {
        int r = m0 + tr * 8 + i;
        if (r >= N_) break;
        float e0 = acc[i][0], e1 = acc[i][1], e2 = acc[i][2], e3 = acc[i][3];
        if (addLabels) {
            int lv = g_lvl[t][r];
            float l0 = (lv == 0) ? 1.0f : 0.0f;
            float l1 = (lv > 0 && lv < BIG_) ? 1.0f : 0.0f;
            e0 += l0 * w64.x + l1 * w65.x;
            e1 += l0 * w64.y + l1 * w65.y;
            e2 += l0 * w64.z + l1 * w65.z;
            e3 += l0 * w64.w + l1 * w65.w;
        }
        float d = g_dinv[t][r];
        float4 o = make_float4(e0 * d, e1 * d, e2 * d, e3 * d);
        *(float4*)&out[(size_t)r * H_ + tc * 4] = o;
    }
}

// ---------------- SpMM + combine: out[n,c] = relu(dinv[n]*(sum g[src,c] + g[n,c]) + b[c]) ----
__global__ void __launch_bounds__(128) k_spmm(const float* __restrict__ gbase,
                                              const float* __restrict__ bias,
                                              float* __restrict__ outBase) {
    int t = blockIdx.y;
    const float* g = gbase + (size_t)t * N_ * H_;
    float* out = outBase + (size_t)t * N_ * H_;
    int row = blockIdx.x;
    int c = threadIdx.x;
    int s0 = g_rowptr[t][row], s1 = g_rowptr[t][row + 1];
    __shared__ int srcs[128];
    float a0 = 0.f, a1 = 0.f, a2 = 0.f, a3 = 0.f;
    for (int base = s0; base < s1; base += 128) {
        int nn = min(128, s1 - base);
        if (c < nn) srcs[c] = g_csrsrc[t][base + c];
        __syncthreads();
        int j = 0;
        for (; j + 4 <= nn; j += 4) {
            a0 += g[(size_t)srcs[j] * H_ + c];
            a1 += g[(size_t)srcs[j + 1] * H_ + c];
            a2 += g[(size_t)srcs[j + 2] * H_ + c];
            a3 += g[(size_t)srcs[j + 3] * H_ + c];
        }
        for (; j < nn; j++) a0 += g[(size_t)srcs[j] * H_ + c];
        __syncthreads();
    }
    float acc = (a0 + a1) + (a2 + a3);
    float d = g_dinv[t][row];
    float v = fmaf(d, acc + g[(size_t)row * H_ + c], bias[c]);
    out[(size_t)row * H_ + c] = fmaxf(v, 0.0f);
}

// ---------------- argmax over subgraph of h2[:, H-1] (first-index tie-break) ----------------
__global__ void k_argmax(const float* __restrict__ h2base) {
    int t = blockIdx.y;
    const float* h2 = h2base + (size_t)t * N_ * H_;
    int i = blockIdx.x * blockDim.x + threadIdx.x;
    unsigned long long p = 0ULL;
    if (i < N_ && g_dinv[t][i] > 0.0f) {
        float v = h2[(size_t)i * H_ + (H_ - 1)];  // relu'd -> >= 0, bits monotone
        p = ((unsigned long long)__float_as_uint(v) << 32) |
            (unsigned int)(0x7fffffff - i);
    }
    __shared__ unsigned long long s[256];
    s[threadIdx.x] = p;
    __syncthreads();
    for (int off = 128; off; off >>= 1) {
        if (threadIdx.x < off) {
            unsigned long long o = s[threadIdx.x + off];
            if (o > s[threadIdx.x]) s[threadIdx.x] = o;
        }
        __syncthreads();
    }
    if (threadIdx.x == 0) atomicMax(&g_argmax[t], s[0]);
}

__global__ void k_extract(const float* __restrict__ h2base) {
    int t = blockIdx.x;
    const float* h2 = h2base + (size_t)t * N_ * H_;
    int top = 0x7fffffff - (int)(g_argmax[t] & 0x7fffffffULL);
    g_seq[t * H_ + threadIdx.x] = h2[(size_t)top * H_ + threadIdx.x];
}

// ---------------- GRU + MLP head ----------------
__device__ __forceinline__ float warp_sum(float v) {
    v += __shfl_down_sync(0xffffffffu, v, 16);
    v += __shfl_down_sync(0xffffffffu, v, 8);
    v += __shfl_down_sync(0xffffffffu, v, 4);
    v += __shfl_down_sync(0xffffffffu, v, 2);
    v += __shfl_down_sync(0xffffffffu, v, 1);
    return v;
}

__global__ void __launch_bounds__(128) k_final(const float* __restrict__ Wih,
                                               const float* __restrict__ Whh,
                                               const float* __restrict__ bih,
                                               const float* __restrict__ bhh,
                                               const float* __restrict__ Wc1,
                                               const float* __restrict__ bc1,
                                               const float* __restrict__ Wc2,
                                               const float* __restrict__ bc2,
                                               float* __restrict__ out) {
    __shared__ float h[H_], xt[H_], sgi[3 * H_], sgh[3 * H_], hid[H_ / 2];
    int tid = threadIdx.x, lane = tid & 31, w = tid >> 5;
    h[tid] = 0.0f;
    __syncthreads();
    for (int t = 0; t < T_; t++) {
        xt[tid] = g_seq[t * H_ + tid];
        __syncthreads();
        for (int o = w; o < 3 * H_; o += 4) {
            float si = 0.f, sh = 0.f;
            for (int k = lane; k < H_; k += 32) {
                si += xt[k] * Wih[(size_t)o * H_ + k];
                sh += h[k] * Whh[(size_t)o * H_ + k];
            }
            si = warp_sum(si);
            sh = warp_sum(sh);
            if (lane == 0) {
                sgi[o] = si + bih[o];
                sgh[o] = sh + bhh[o];
            }
        }
        __syncthreads();
        float r = 1.0f / (1.0f + expf(-(sgi[tid] + sgh[tid])));
        float z = 1.0f / (1.0f + expf(-(sgi[tid + H_] + sgh[tid + H_])));
        float n = tanhf(sgi[tid + 2 * H_] + r * sgh[tid + 2 * H_]);
        float hn = (1.0f - z) * n + z * h[tid];
        __syncthreads();
        h[tid] = hn;
        __syncthreads();
    }
    if (tid < H_ / 2) {
        float s = bc1[tid];
        for (int k = 0; k < H_; k++) s += h[k] * Wc1[(size_t)k * (H_ / 2) + tid];
        hid[tid] = fmaxf(s, 0.0f);
    }
    __syncthreads();
    if (tid == 0) {
        float s = bc2[0];
        for (int j = 0; j < H_ / 2; j++) s += hid[j] * Wc2[j];
        out[0] = 1.0f / (1.0f + expf(-s));
    }
}

// ---------------- launch ----------------
extern "C" void kernel_launch(void* const* d_in, const int* in_sizes, int n_in,
                              void* d_out, int out_size) {
    const float* x   = (const float*)d_in[0];
    const int*   ei  = (const int*)d_in[1];
    const int*   tgt = (const int*)d_in[2];
    const float* W1  = (const float*)d_in[3];
    const float* b1  = (const float*)d_in[4];
    const float* W2  = (const float*)d_in[5];
    const float* b2  = (const float*)d_in[6];
    const float* Wih = (const float*)d_in[7];
    const float* Whh = (const float*)d_in[8];
    const float* bih = (const float*)d_in[9];
    const float* bhh = (const float*)d_in[10];
    const float* Wc1 = (const float*)d_in[11];
    const float* bc1 = (const float*)d_in[12];
    const float* Wc2 = (const float*)d_in[13];
    const float* bc2 = (const float*)d_in[14];
    float* out = (float*)d_out;

    float *buf1 = nullptr, *buf2 = nullptr;
    cudaGetSymbolAddress((void**)&buf1, g_buf1);
    cudaGetSymbolAddress((void**)&buf2, g_buf2);

    const dim3 GN((N_ + 255) / 256, T_);
    const dim3 GE((E_ + 255) / 256, T_);
    const dim3 GM((N_ + BM - 1) / BM, T_);

    k_reset<<<GN, 256>>>();
    k_seed<<<T_, 64>>>(tgt);
    k_prop<<<GE, 256>>>(ei, 1);
    k_prop<<<GE, 256>>>(ei, 2);
    k_count<<<GE, 256>>>(ei);
    k_scan<<<T_, 1024>>>();
    k_fill<<<GE, 256>>>(ei);

    k_gemm<<<GM, 256>>>(x, F_, W1, 1, buf1);        // g1 = dinv * (xl @ W1)
    k_spmm<<<dim3(N_, T_), 128>>>(buf1, b1, buf2);  // h1
    k_gemm<<<GM, 256>>>(buf2, H_, W2, 0, buf1);     // g2 = dinv * (h1 @ W2)
    k_spmm<<<dim3(N_, T_), 128>>>(buf1, b2, buf2);  // h2
    k_argmax<<<GN, 256>>>(buf2);
    k_extract<<<T_, 128>>>(buf2);
    k_final<<<1, 128>>>(Wih, Whh, bih, bhh, Wc1, bc1, Wc2, bc2, out);
}

// round 4
// speedup vs baseline: 1.5368x; 1.2843x over previous
#include <cuda_runtime.h>
#include <math.h>

#define T_ 6
#define N_ 20000
#define E_ 400000
#define F_ 64
#define C_ 64
#define H_ 128
#define BIG_ 0x3fffffff

// ---------------- scratch (device globals; no allocation) ----------------
__device__ __align__(128) int   g_lvl[T_][N_];
__device__ __align__(128) int   g_count[T_][N_];
__device__ __align__(128) int   g_rowptr[T_][N_ + 1];
__device__ __align__(128) int   g_cursor[T_][N_];
__device__ __align__(128) int   g_csrsrc[T_][E_];
__device__ __align__(128) float g_dinv[T_][N_];
__device__ __align__(128) float g_buf1[T_][N_ * H_];   // g1 = dinv*(xl@W1)
__device__ __align__(128) float g_buf2[T_][N_ * H_];   // h1
__device__ __align__(128) float g_col[T_][N_];         // g2col = dinv*(h1@W2[:,127])
__device__ unsigned long long   g_argmax[T_];
__device__ __align__(128) float g_seq[T_ * H_];

// ---------------- per-snapshot setup (batched over t = blockIdx.y) ----------------
__global__ void k_reset() {
    int t = blockIdx.y;
    int i = blockIdx.x * blockDim.x + threadIdx.x;
    if (i < N_) { g_lvl[t][i] = BIG_; g_count[t][i] = 0; }
    if (i == 0) g_argmax[t] = 0ULL;
}

__global__ void k_seed(const int* __restrict__ tgt) {
    int t = blockIdx.x;
    int i = threadIdx.x;
    if (i < C_) g_lvl[t][tgt[t * C_ + i]] = 0;
}

// Level-stamped BFS iteration k: a node is "in" at start of iter k iff lvl < k.
// Writes during iter k are exactly value k, so non-atomic reads cannot cause
// over-propagation (predicate lvl<k only sees earlier iterations).
__global__ void k_prop(const int* __restrict__ ei, int k) {
    int t = blockIdx.y;
    int i = blockIdx.x * blockDim.x + threadIdx.x;
    if (i >= E_) return;
    const int* src = ei + (size_t)t * 2 * E_;
    const int* dst = src + E_;
    int s = src[i], d = dst[i];
    int ls = g_lvl[t][s], ld = g_lvl[t][d];
    if (ls < k && ld > k) atomicMin(&g_lvl[t][d], k);
    if (ld < k && ls > k) atomicMin(&g_lvl[t][s], k);
}

// in-degree over subgraph edges (directed, dst side) == CSR histogram
__global__ void k_count(const int* __restrict__ ei) {
    int t = blockIdx.y;
    int i = blockIdx.x * blockDim.x + threadIdx.x;
    if (i >= E_) return;
    const int* src = ei + (size_t)t * 2 * E_;
    const int* dst = src + E_;
    int s = src[i], d = dst[i];
    if (g_lvl[t][s] < BIG_ && g_lvl[t][d] < BIG_) atomicAdd(&g_count[t][d], 1);
}

// per-snapshot single-block exclusive scan over g_count -> rowptr/cursor; also dinv.
__global__ void k_scan() {
    int t = blockIdx.x;
    const int CH = 20;  // 1024 * 20 >= 20000
    __shared__ int s[1024];
    int tid = threadIdx.x;
    int base = tid * CH;
    int loc[CH];
    int sum = 0;
#pragma unroll
    for (int i = 0; i < CH; i++) {
        int idx = base + i;
        int c = (idx < N_) ? g_count[t][idx] : 0;
        loc[i] = sum;
        sum += c;
    }
    s[tid] = sum;
    __syncthreads();
    for (int off = 1; off < 1024; off <<= 1) {
        int v = (tid >= off) ? s[tid - off] : 0;
        __syncthreads();
        s[tid] += v;
        __syncthreads();
    }
    int excl = s[tid] - sum;
#pragma unroll
    for (int i = 0; i < CH; i++) {
        int idx = base + i;
        if (idx < N_) {
            int o = excl + loc[i];
            g_rowptr[t][idx] = o;
            g_cursor[t][idx] = o;
            int lv = g_lvl[t][idx];
            g_dinv[t][idx] = (lv < BIG_) ? rsqrtf((float)g_count[t][idx] + 1.0f) : 0.0f;
        }
    }
    if (tid == 1023) g_rowptr[t][N_] = s[1023];
}

__global__ void k_fill(const int* __restrict__ ei) {
    int t = blockIdx.y;
    int i = blockIdx.x * blockDim.x + threadIdx.x;
    if (i >= E_) return;
    const int* src = ei + (size_t)t * 2 * E_;
    const int* dst = src + E_;
    int s = src[i], d = dst[i];
    if (g_lvl[t][s] < BIG_ && g_lvl[t][d] < BIG_) {
        int p = atomicAdd(&g_cursor[t][d], 1);
        g_csrsrc[t][p] = s;
    }
}

// ---------------- GEMM1: g1[n,:] = dinv[n] * (xl[n,:] @ W1) ----------------
#define BM 64
#define KC 32
__global__ void __launch_bounds__(256) k_gemm(const float* __restrict__ Abase, int K,
                                              const float* __restrict__ W, int addLabels,
                                              float* __restrict__ outBase) {
    int t = blockIdx.y;
    const float* A = Abase + (size_t)t * N_ * K;
    float* out = outBase + (size_t)t * N_ * H_;

    __shared__ float As[KC][BM + 4];
    __shared__ float Bs[KC][H_];
    int tid = threadIdx.x;
    int tc = tid & 31;
    int tr = tid >> 5;
    int m0 = blockIdx.x * BM;

    float acc[8][4];
#pragma unroll
    for (int i = 0; i < 8; i++)
#pragma unroll
        for (int j = 0; j < 4; j++) acc[i][j] = 0.0f;

    for (int kb = 0; kb < K; kb += KC) {
#pragma unroll
        for (int i = 0; i < 2; i++) {
            int e = tid + i * 256;
            int r = e >> 3;
            int kq = (e & 7) * 4;
            int gr = m0 + r;
            float4 v = make_float4(0.f, 0.f, 0.f, 0.f);
            if (gr < N_) v = *(const float4*)&A[(size_t)gr * K + kb + kq];
            As[kq + 0][r] = v.x;
            As[kq + 1][r] = v.y;
            As[kq + 2][r] = v.z;
            As[kq + 3][r] = v.w;
        }
#pragma unroll
        for (int i = 0; i < 4; i++) {
            int e = tid + i * 256;
            int kr = e >> 5;
            int cq = (e & 31) * 4;
            *(float4*)&Bs[kr][cq] = *(const float4*)&W[(size_t)(kb + kr) * H_ + cq];
        }
        __syncthreads();
#pragma unroll
        for (int k = 0; k < KC; k++) {
            float4 b = *(float4*)&Bs[k][tc * 4];
            // vectorized As reads: rows tr*8..tr*8+7 are contiguous, 16B aligned
            float4 al = *(float4*)&As[k][tr * 8];
            float4 ah = *(float4*)&As[k][tr * 8 + 4];
            float a[8] = {al.x, al.y, al.z, al.w, ah.x, ah.y, ah.z, ah.w};
#pragma unroll
            for (int i = 0; i < 8; i++) {
                acc[i][0] = fmaf(a[i], b.x, acc[i][0]);
                acc[i][1] = fmaf(a[i], b.y, acc[i][1]);
                acc[i][2] = fmaf(a[i], b.z, acc[i][2]);
                acc[i][3] = fmaf(a[i], b.w, acc[i][3]);
            }
        }
        __syncthreads();
    }

    float4 w64 = make_float4(0.f, 0.f, 0.f, 0.f);
    float4 w65 = make_float4(0.f, 0.f, 0.f, 0.f);
    if (addLabels) {
        w64 = *(const float4*)&W[(size_t)64 * H_ + tc * 4];
        w65 = *(const float4*)&W[(size_t)65 * H_ + tc * 4];
    }
#pragma unroll
    for (int i = 0; i < 8; i++) {
        int r = m0 + tr * 8 + i;
        if (r >= N_) break;
        float e0 = acc[i][0], e1 = acc[i][1], e2 = acc[i][2], e3 = acc[i][3];
        if (addLabels) {
            int lv = g_lvl[t][r];
            float l0 = (lv == 0) ? 1.0f : 0.0f;
            float l1 = (lv > 0 && lv < BIG_) ? 1.0f : 0.0f;
            e0 += l0 * w64.x + l1 * w65.x;
            e1 += l0 * w64.y + l1 * w65.y;
            e2 += l0 * w64.z + l1 * w65.z;
            e3 += l0 * w64.w + l1 * w65.w;
        }
        float d = g_dinv[t][r];
        float4 o = make_float4(e0 * d, e1 * d, e2 * d, e3 * d);
        *(float4*)&out[(size_t)r * H_ + tc * 4] = o;
    }
}

__device__ __forceinline__ float warp_sum(float v) {
    v += __shfl_down_sync(0xffffffffu, v, 16);
    v += __shfl_down_sync(0xffffffffu, v, 8);
    v += __shfl_down_sync(0xffffffffu, v, 4);
    v += __shfl_down_sync(0xffffffffu, v, 2);
    v += __shfl_down_sync(0xffffffffu, v, 1);
    return v;
}

// ---------------- SpMM1 (warp-per-row, float4) + fused g2col epilogue ----------------
// h1[n,c] = relu(dinv[n]*(sum_{src->n} g1[src,c] + g1[n,c]) + b1[c])
// g2col[n] = dinv[n] * sum_c h1[n,c]*W2[c,127]
__global__ void __launch_bounds__(256) k_spmm1(const float* __restrict__ gbase,
                                               const float* __restrict__ b1,
                                               const float* __restrict__ W2,
                                               float* __restrict__ h1base) {
    int t = blockIdx.y;
    const float* g = gbase + (size_t)t * N_ * H_;
    float* h1 = h1base + (size_t)t * N_ * H_;

    __shared__ float w2c[H_];
    int tid = threadIdx.x;
    if (tid < H_) w2c[tid] = W2[(size_t)tid * H_ + (H_ - 1)];
    __syncthreads();

    int warp = tid >> 5, lane = tid & 31;
    int row = blockIdx.x * 8 + warp;
    if (row >= N_) return;

    int s0 = g_rowptr[t][row], s1 = g_rowptr[t][row + 1];
    const int* __restrict__ csr = g_csrsrc[t];
    int co = lane * 4;

    float4 a0 = make_float4(0.f, 0.f, 0.f, 0.f);
    float4 a1 = make_float4(0.f, 0.f, 0.f, 0.f);
    float4 a2 = make_float4(0.f, 0.f, 0.f, 0.f);
    float4 a3 = make_float4(0.f, 0.f, 0.f, 0.f);
    int j = s0;
    for (; j + 4 <= s1; j += 4) {
        int i0 = csr[j], i1 = csr[j + 1], i2 = csr[j + 2], i3 = csr[j + 3];
        float4 v0 = *(const float4*)&g[(size_t)i0 * H_ + co];
        float4 v1 = *(const float4*)&g[(size_t)i1 * H_ + co];
        float4 v2 = *(const float4*)&g[(size_t)i2 * H_ + co];
        float4 v3 = *(const float4*)&g[(size_t)i3 * H_ + co];
        a0.x += v0.x; a0.y += v0.y; a0.z += v0.z; a0.w += v0.w;
        a1.x += v1.x; a1.y += v1.y; a1.z += v1.z; a1.w += v1.w;
        a2.x += v2.x; a2.y += v2.y; a2.z += v2.z; a2.w += v2.w;
        a3.x += v3.x; a3.y += v3.y; a3.z += v3.z; a3.w += v3.w;
    }
    for (; j < s1; j++) {
        float4 v = *(const float4*)&g[(size_t)csr[j] * H_ + co];
        a0.x += v.x; a0.y += v.y; a0.z += v.z; a0.w += v.w;
    }
    float4 self = *(const float4*)&g[(size_t)row * H_ + co];
    float ax = (a0.x + a1.x) + (a2.x + a3.x) + self.x;
    float ay = (a0.y + a1.y) + (a2.y + a3.y) + self.y;
    float az = (a0.z + a1.z) + (a2.z + a3.z) + self.z;
    float aw = (a0.w + a1.w) + (a2.w + a3.w) + self.w;

    float d = g_dinv[t][row];
    float4 bb = *(const float4*)&b1[co];
    float4 v;
    v.x = fmaxf(fmaf(d, ax, bb.x), 0.f);
    v.y = fmaxf(fmaf(d, ay, bb.y), 0.f);
    v.z = fmaxf(fmaf(d, az, bb.z), 0.f);
    v.w = fmaxf(fmaf(d, aw, bb.w), 0.f);
    *(float4*)&h1[(size_t)row * H_ + co] = v;

    float dot = v.x * w2c[co] + v.y * w2c[co + 1] + v.z * w2c[co + 2] + v.w * w2c[co + 3];
    dot = warp_sum(dot);
    if (lane == 0) g_col[t][row] = d * dot;
}

// ---------------- layer-2 scalar aggregation + fused argmax ----------------
// h2col[n] = relu(dinv[n]*(sum g2col[src] + g2col[n]) + b2[127]); argmax over subgraph
__global__ void __launch_bounds__(256) k_col_argmax(const float* __restrict__ b2) {
    int t = blockIdx.y;
    int tid = threadIdx.x;
    int warp = tid >> 5, lane = tid & 31;
    int row = blockIdx.x * 8 + warp;
    unsigned long long p = 0ULL;
    float b = b2[H_ - 1];
    if (row < N_) {
        int s0 = g_rowptr[t][row], s1 = g_rowptr[t][row + 1];
        const int* __restrict__ csr = g_csrsrc[t];
        float s = 0.f;
        for (int j = s0 + lane; j < s1; j += 32) s += g_col[t][csr[j]];
        s = warp_sum(s);
        if (lane == 0) {
            float d = g_dinv[t][row];
            if (d > 0.f) {
                float v = fmaxf(fmaf(d, s + g_col[t][row], b), 0.f);
                p = ((unsigned long long)__float_as_uint(v) << 32) |
                    (unsigned int)(0x7fffffff - row);
            }
        }
    }
    __shared__ unsigned long long sm[8];
    if (lane == 0) sm[warp] = p;
    __syncthreads();
    if (tid == 0) {
        unsigned long long m = sm[0];
#pragma unroll
        for (int i = 1; i < 8; i++) m = (sm[i] > m) ? sm[i] : m;
        if (m) atomicMax(&g_argmax[t], m);
    }
}

// ---------------- reconstruct h2[top,:] and write g_seq[t] ----------------
// svec = sum_{s in N(top)} dinv[s]*h1[s,:] + dinv[top]*h1[top,:]
// h2[top,c] = relu(dinv[top]*(svec @ W2)[c] + b2[c])
__global__ void __launch_bounds__(128) k_top(const float* __restrict__ h1base,
                                             const float* __restrict__ W2,
                                             const float* __restrict__ b2) {
    int t = blockIdx.x;
    const float* h1 = h1base + (size_t)t * N_ * H_;
    int top = 0x7fffffff - (int)(g_argmax[t] & 0x7fffffffULL);
    int c = threadIdx.x;
    __shared__ float svec[H_];

    int s0 = g_rowptr[t][top], s1 = g_rowptr[t][top + 1];
    float dtop = g_dinv[t][top];
    float acc = dtop * h1[(size_t)top * H_ + c];
    for (int j = s0; j < s1; j++) {
        int s = g_csrsrc[t][j];
        acc += g_dinv[t][s] * h1[(size_t)s * H_ + c];
    }
    svec[c] = acc;
    __syncthreads();

    float o = 0.f;
#pragma unroll 4
    for (int k = 0; k < H_; k++) o = fmaf(svec[k], W2[(size_t)k * H_ + c], o);
    g_seq[t * H_ + c] = fmaxf(fmaf(dtop, o, b2[c]), 0.f);
}

// ---------------- GRU + MLP head ----------------
__global__ void __launch_bounds__(128) k_final(const float* __restrict__ Wih,
                                               const float* __restrict__ Whh,
                                               const float* __restrict__ bih,
                                               const float* __restrict__ bhh,
                                               const float* __restrict__ Wc1,
                                               const float* __restrict__ bc1,
                                               const float* __restrict__ Wc2,
                                               const float* __restrict__ bc2,
                                               float* __restrict__ out) {
    __shared__ float h[H_], xt[H_], sgi[3 * H_], sgh[3 * H_], hid[H_ / 2];
    int tid = threadIdx.x, lane = tid & 31, w = tid >> 5;
    h[tid] = 0.0f;
    __syncthreads();
    for (int t = 0; t < T_; t++) {
        xt[tid] = g_seq[t * H_ + tid];
        __syncthreads();
        for (int o = w; o < 3 * H_; o += 4) {
            float si = 0.f, sh = 0.f;
            for (int k = lane; k < H_; k += 32) {
                si += xt[k] * Wih[(size_t)o * H_ + k];
                sh += h[k] * Whh[(size_t)o * H_ + k];
            }
            si = warp_sum(si);
            sh = warp_sum(sh);
            if (lane == 0) {
                sgi[o] = si + bih[o];
                sgh[o] = sh + bhh[o];
            }
        }
        __syncthreads();
        float r = 1.0f / (1.0f + expf(-(sgi[tid] + sgh[tid])));
        float z = 1.0f / (1.0f + expf(-(sgi[tid + H_] + sgh[tid + H_])));
        float n = tanhf(sgi[tid + 2 * H_] + r * sgh[tid + 2 * H_]);
        float hn = (1.0f - z) * n + z * h[tid];
        __syncthreads();
        h[tid] = hn;
        __syncthreads();
    }
    if (tid < H_ / 2) {
        float s = bc1[tid];
        for (int k = 0; k < H_; k++) s += h[k] * Wc1[(size_t)k * (H_ / 2) + tid];
        hid[tid] = fmaxf(s, 0.0f);
    }
    __syncthreads();
    if (tid == 0) {
        float s = bc2[0];
        for (int j = 0; j < H_ / 2; j++) s += hid[j] * Wc2[j];
        out[0] = 1.0f / (1.0f + expf(-s));
    }
}

// ---------------- launch ----------------
extern "C" void kernel_launch(void* const* d_in, const int* in_sizes, int n_in,
                              void* d_out, int out_size) {
    const float* x   = (const float*)d_in[0];
    const int*   ei  = (const int*)d_in[1];
    const int*   tgt = (const int*)d_in[2];
    const float* W1  = (const float*)d_in[3];
    const float* b1  = (const float*)d_in[4];
    const float* W2  = (const float*)d_in[5];
    const float* b2  = (const float*)d_in[6];
    const float* Wih = (const float*)d_in[7];
    const float* Whh = (const float*)d_in[8];
    const float* bih = (const float*)d_in[9];
    const float* bhh = (const float*)d_in[10];
    const float* Wc1 = (const float*)d_in[11];
    const float* bc1 = (const float*)d_in[12];
    const float* Wc2 = (const float*)d_in[13];
    const float* bc2 = (const float*)d_in[14];
    float* out = (float*)d_out;

    float *buf1 = nullptr, *buf2 = nullptr;
    cudaGetSymbolAddress((void**)&buf1, g_buf1);
    cudaGetSymbolAddress((void**)&buf2, g_buf2);

    const dim3 GN((N_ + 255) / 256, T_);
    const dim3 GE((E_ + 255) / 256, T_);
    const dim3 GM((N_ + BM - 1) / BM, T_);
    const dim3 GR((N_ + 7) / 8, T_);

    k_reset<<<GN, 256>>>();
    k_seed<<<T_, 64>>>(tgt);
    k_prop<<<GE, 256>>>(ei, 1);
    k_prop<<<GE, 256>>>(ei, 2);
    k_count<<<GE, 256>>>(ei);
    k_scan<<<T_, 1024>>>();
    k_fill<<<GE, 256>>>(ei);

    k_gemm<<<GM, 256>>>(x, F_, W1, 1, buf1);      // g1 = dinv * (xl @ W1)
    k_spmm1<<<GR, 256>>>(buf1, b1, W2, buf2);     // h1 + fused g2col
    k_col_argmax<<<GR, 256>>>(b2);                // layer-2 scalar agg + argmax
    k_top<<<T_, 128>>>(buf2, W2, b2);             // reconstruct h2[top,:]
    k_final<<<1, 128>>>(Wih, Whh, bih, bhh, Wc1, bc1, Wc2, bc2, out);
}